// round 5
// baseline (speedup 1.0000x reference)
#include <cuda_runtime.h>
#include <math.h>

#define N_ATOMS 5000
#define N_PAIRS 200000
#define NF 80
#define ND 20
#define TROW 1680          // 20*80 interaction slots + 80 self-interaction slots
#define HARD_CUT_F 6.5f
#define ATOMS_PER_BLK 4

// Scratch: T[j, s*80+o] for s<20; T[j, 1600+o] = self-interaction row.
// 5000 * 1680 * 4 B = 33.6 MB (static device array — no runtime allocation).
__device__ float g_T[(size_t)N_ATOMS * TROW];

// ---------------------------------------------------------------------------
// Kernel 1: T[m, n] = sum_f A[m, f] * B[n, f]
//   A = in_features [5000, 80]
//   B row n: n < 1600 -> int_weights flat (s*80+o)*80+f ; n in [1600,1680) -> selfint_w
// Tiled 64x64, K=80 resident in smem, 4x4 register blocking.
// ---------------------------------------------------------------------------
__global__ __launch_bounds__(256) void tmat_kernel(
    const float* __restrict__ A,
    const float* __restrict__ Wint,
    const float* __restrict__ Wself)
{
    __shared__ float As[64][84];   // [m][k], stride 84 (16B-aligned rows, de-banked)
    __shared__ float Bs[64][84];   // [n][k]

    const int m0 = blockIdx.x * 64;
    const int n0 = blockIdx.y * 64;
    const int t  = threadIdx.x;

    // Load A tile (64 rows x 80 cols) as float4
    for (int i = t; i < 64 * 20; i += 256) {
        int r = i / 20, c = i % 20;
        int m = m0 + r;
        float4 v = make_float4(0.f, 0.f, 0.f, 0.f);
        if (m < N_ATOMS) v = ((const float4*)A)[m * 20 + c];
        *(float4*)&As[r][c * 4] = v;
    }
    // Load B tile (64 rows x 80 cols)
    for (int i = t; i < 64 * 20; i += 256) {
        int r = i / 20, c = i % 20;
        int n = n0 + r;
        float4 v = make_float4(0.f, 0.f, 0.f, 0.f);
        if (n < 1600)      v = ((const float4*)Wint)[n * 20 + c];
        else if (n < TROW) v = ((const float4*)Wself)[(n - 1600) * 20 + c];
        *(float4*)&Bs[r][c * 4] = v;
    }
    __syncthreads();

    const int tx = t % 16;   // n direction
    const int ty = t / 16;   // m direction

    float acc[4][4];
#pragma unroll
    for (int i = 0; i < 4; i++)
#pragma unroll
        for (int j = 0; j < 4; j++) acc[i][j] = 0.f;

#pragma unroll 5
    for (int k4 = 0; k4 < 20; k4++) {
        float4 a4[4], b4[4];
#pragma unroll
        for (int i = 0; i < 4; i++) a4[i] = *(const float4*)&As[ty * 4 + i][k4 * 4];
#pragma unroll
        for (int j = 0; j < 4; j++) b4[j] = *(const float4*)&Bs[tx * 4 + j][k4 * 4];
#pragma unroll
        for (int i = 0; i < 4; i++) {
#pragma unroll
            for (int j = 0; j < 4; j++) {
                acc[i][j] = fmaf(a4[i].x, b4[j].x, acc[i][j]);
                acc[i][j] = fmaf(a4[i].y, b4[j].y, acc[i][j]);
                acc[i][j] = fmaf(a4[i].z, b4[j].z, acc[i][j]);
                acc[i][j] = fmaf(a4[i].w, b4[j].w, acc[i][j]);
            }
        }
    }

#pragma unroll
    for (int i = 0; i < 4; i++) {
        int m = m0 + ty * 4 + i;
        if (m >= N_ATOMS) continue;
#pragma unroll
        for (int j = 0; j < 4; j++) {
            int n = n0 + tx * 4 + j;
            if (n < TROW) g_T[(size_t)m * TROW + n] = acc[i][j];
        }
    }
}

// ---------------------------------------------------------------------------
// Kernel 2: one warp per atom, 4 warps per CTA. pair_first is sorted ->
// binary search pair range (lane 0, broadcast). Lanes 0..19 each own 4 output
// channels (float4). Pair metadata (j, dist, coord) software-pipelined one
// iteration ahead so its latency hides under the 20-step T-row reduction.
// Epilogue fuses self/bias/vecscale/sqrt.
// ---------------------------------------------------------------------------
__global__ __launch_bounds__(ATOMS_PER_BLK * 32) void pair_kernel(
    const float* __restrict__ dist,
    const float* __restrict__ coord,
    const float* __restrict__ selfb,
    const float* __restrict__ vecscales,
    const float* __restrict__ mu,
    const float* __restrict__ sigma,
    const int*   __restrict__ pf,
    const int*   __restrict__ ps,
    float*       __restrict__ out)
{
    const int warp = threadIdx.x >> 5;
    const int lane = threadIdx.x & 31;
    const int a    = blockIdx.x * ATOMS_PER_BLK + warp;
    if (a >= N_ATOMS) return;

    __shared__ float sense_sh[ATOMS_PER_BLK][ND];

    // lower_bound(pf, a) and lower_bound(pf, a+1): lane 0 searches, broadcast.
    int start = 0, end = 0;
    if (lane == 0) {
        int lo = 0, hi = N_PAIRS;
        while (lo < hi) { int mid = (lo + hi) >> 1; if (pf[mid] < a) lo = mid + 1; else hi = mid; }
        start = lo;
        hi = N_PAIRS;
        while (lo < hi) { int mid = (lo + hi) >> 1; if (pf[mid] < a + 1) lo = mid + 1; else hi = mid; }
        end = lo;
    }
    start = __shfl_sync(0xffffffffu, start, 0);
    end   = __shfl_sync(0xffffffffu, end,   0);

    float mu_l = 0.f, cexp = 0.f;
    if (lane < ND) {
        mu_l = mu[lane];
        float sg = sigma[lane];
        cexp = -0.5f / (sg * sg);
    }

    float4 accS = make_float4(0.f, 0.f, 0.f, 0.f);
    float4 accX = accS, accY = accS, accZ = accS;

    // --- software pipeline: prefetch pair metadata one iteration ahead ---
    int   j_n = 0;
    float d_n = 1.f, cx_n = 0.f, cy_n = 0.f, cz_n = 0.f;
    if (start < end) {
        j_n  = ps[start];
        d_n  = dist[start];
        cx_n = coord[3 * start + 0];
        cy_n = coord[3 * start + 1];
        cz_n = coord[3 * start + 2];
    }

    for (int p = start; p < end; p++) {
        const int   j  = j_n;
        const float d  = d_n;
        const float inv = __fdividef(1.0f, d);
        const float ux = cx_n * inv;
        const float uy = cy_n * inv;
        const float uz = cz_n * inv;

        if (p + 1 < end) {   // issue next pair's loads early
            j_n  = ps[p + 1];
            d_n  = dist[p + 1];
            cx_n = coord[3 * (p + 1) + 0];
            cy_n = coord[3 * (p + 1) + 1];
            cz_n = coord[3 * (p + 1) + 2];
        }

        __syncwarp();  // WAR: previous iteration's sense_sh reads are done
        if (lane < ND) {
            float df  = inv - mu_l;
            float cut = (d < HARD_CUT_F)
                      ? 0.5f * (__cosf((3.14159265358979323846f / HARD_CUT_F) * d) + 1.0f)
                      : 0.0f;
            sense_sh[warp][lane] = __expf(cexp * df * df) * cut;
        }
        __syncwarp();  // sense_sh visible to all lanes

        if (lane < ND) {
            const float4* Trow = (const float4*)(g_T + (size_t)j * TROW);
            float4 v = make_float4(0.f, 0.f, 0.f, 0.f);
#pragma unroll
            for (int s = 0; s < ND; s++) {
                float  sv = sense_sh[warp][s];
                float4 tv = Trow[s * 20 + lane];
                v.x = fmaf(sv, tv.x, v.x);
                v.y = fmaf(sv, tv.y, v.y);
                v.z = fmaf(sv, tv.z, v.z);
                v.w = fmaf(sv, tv.w, v.w);
            }
            accS.x += v.x; accS.y += v.y; accS.z += v.z; accS.w += v.w;
            accX.x = fmaf(ux, v.x, accX.x); accX.y = fmaf(ux, v.y, accX.y);
            accX.z = fmaf(ux, v.z, accX.z); accX.w = fmaf(ux, v.w, accX.w);
            accY.x = fmaf(uy, v.x, accY.x); accY.y = fmaf(uy, v.y, accY.y);
            accY.z = fmaf(uy, v.z, accY.z); accY.w = fmaf(uy, v.w, accY.w);
            accZ.x = fmaf(uz, v.x, accZ.x); accZ.y = fmaf(uz, v.y, accZ.y);
            accZ.z = fmaf(uz, v.z, accZ.z); accZ.w = fmaf(uz, v.w, accZ.w);
        }
    }

    if (lane < ND) {
        // self-interaction slot precomputed in T (cols 1600..1679)
        const float4 sf = *(const float4*)(g_T + (size_t)a * TROW + 1600 + 4 * lane);
        const float4 vs = ((const float4*)vecscales)[lane];
        const float4 bb = ((const float4*)selfb)[lane];
        float4 o4;
        o4.x = accS.x + vs.x * sqrtf(accX.x * accX.x + accY.x * accY.x + accZ.x * accZ.x + 1e-30f) + sf.x + bb.x;
        o4.y = accS.y + vs.y * sqrtf(accX.y * accX.y + accY.y * accY.y + accZ.y * accZ.y + 1e-30f) + sf.y + bb.y;
        o4.z = accS.z + vs.z * sqrtf(accX.z * accX.z + accY.z * accY.z + accZ.z * accZ.z + 1e-30f) + sf.z + bb.z;
        o4.w = accS.w + vs.w * sqrtf(accX.w * accX.w + accY.w * accY.w + accZ.w * accZ.w + 1e-30f) + sf.w + bb.w;
        ((float4*)out)[a * 20 + lane] = o4;
    }
}

// ---------------------------------------------------------------------------
extern "C" void kernel_launch(void* const* d_in, const int* in_sizes, int n_in,
                              void* d_out, int out_size)
{
    const float* feat   = (const float*)d_in[0];   // [5000, 80]
    const float* dist   = (const float*)d_in[1];   // [200000]
    const float* coord  = (const float*)d_in[2];   // [200000, 3]
    const float* wint   = (const float*)d_in[3];   // [20, 80, 80]
    const float* wself  = (const float*)d_in[4];   // [80, 80]
    const float* sbias  = (const float*)d_in[5];   // [80]
    const float* vscale = (const float*)d_in[6];   // [80]
    const float* mu     = (const float*)d_in[7];   // [20]
    const float* sigma  = (const float*)d_in[8];   // [20]
    const int*   pf     = (const int*)d_in[9];     // [200000] sorted
    const int*   ps     = (const int*)d_in[10];    // [200000]
    float* out = (float*)d_out;                    // [5000, 80]

    dim3 g1((N_ATOMS + 63) / 64, (TROW + 63) / 64);   // 79 x 27
    tmat_kernel<<<g1, 256>>>(feat, wint, wself);
    pair_kernel<<<(N_ATOMS + ATOMS_PER_BLK - 1) / ATOMS_PER_BLK, ATOMS_PER_BLK * 32>>>(
        dist, coord, sbias, vscale, mu, sigma, pf, ps, out);
}

// round 14
// speedup vs baseline: 1.2519x; 1.2519x over previous
#include <cuda_runtime.h>
#include <math.h>

#define N_ATOMS 5000
#define N_PAIRS 200000
#define NF 80
#define ND 20
#define TROW 1680          // 20*80 interaction slots + 80 self-interaction slots
#define HARD_CUT_F 6.5f
#define ATOMS_PER_BLK 4
#define PI_F 3.14159265358979323846f

// Scratch: T[j, s*80+o] for s<20; T[j, 1600+o] = self-interaction row.
__device__ float g_T[(size_t)N_ATOMS * TROW];

// ---------------------------------------------------------------------------
// Kernel 1: T[m, n] = sum_f A[m, f] * B[n, f]
// k-major shared tiles -> conflict-free LDS.128 in the inner loop.
// 64x64 tile, 4x4 register micro-tile, full K=80 resident.
// ---------------------------------------------------------------------------
__global__ __launch_bounds__(256) void tmat_kernel(
    const float* __restrict__ A,
    const float* __restrict__ Wint,
    const float* __restrict__ Wself)
{
    __shared__ float As[80][68];   // [k][m], pad 68 to stagger store banks
    __shared__ float Bs[80][68];   // [k][n]

    const int m0 = blockIdx.x * 64;
    const int n0 = blockIdx.y * 64;
    const int t  = threadIdx.x;

    // Load + transpose A tile (64 m-rows x 80 k) into k-major smem
    for (int i = t; i < 64 * 20; i += 256) {
        int r = i / 20, c = i % 20;          // r: m-in-tile, c: k-group
        int m = m0 + r;
        float4 v = make_float4(0.f, 0.f, 0.f, 0.f);
        if (m < N_ATOMS) v = ((const float4*)A)[m * 20 + c];
        As[c * 4 + 0][r] = v.x;
        As[c * 4 + 1][r] = v.y;
        As[c * 4 + 2][r] = v.z;
        As[c * 4 + 3][r] = v.w;
    }
    // Load + transpose B tile (64 n-rows x 80 k)
    for (int i = t; i < 64 * 20; i += 256) {
        int r = i / 20, c = i % 20;
        int n = n0 + r;
        float4 v = make_float4(0.f, 0.f, 0.f, 0.f);
        if (n < 1600)      v = ((const float4*)Wint)[n * 20 + c];
        else if (n < TROW) v = ((const float4*)Wself)[(n - 1600) * 20 + c];
        Bs[c * 4 + 0][r] = v.x;
        Bs[c * 4 + 1][r] = v.y;
        Bs[c * 4 + 2][r] = v.z;
        Bs[c * 4 + 3][r] = v.w;
    }
    __syncthreads();

    const int tx = t % 16;   // n direction
    const int ty = t / 16;   // m direction

    float acc[4][4];
#pragma unroll
    for (int i = 0; i < 4; i++)
#pragma unroll
        for (int j = 0; j < 4; j++) acc[i][j] = 0.f;

#pragma unroll 20
    for (int k = 0; k < 80; k++) {
        float4 a = *(const float4*)&As[k][ty * 4];   // 4 m-values (broadcast-friendly)
        float4 b = *(const float4*)&Bs[k][tx * 4];   // 4 n-values (conflict-free)
        acc[0][0] = fmaf(a.x, b.x, acc[0][0]); acc[0][1] = fmaf(a.x, b.y, acc[0][1]);
        acc[0][2] = fmaf(a.x, b.z, acc[0][2]); acc[0][3] = fmaf(a.x, b.w, acc[0][3]);
        acc[1][0] = fmaf(a.y, b.x, acc[1][0]); acc[1][1] = fmaf(a.y, b.y, acc[1][1]);
        acc[1][2] = fmaf(a.y, b.z, acc[1][2]); acc[1][3] = fmaf(a.y, b.w, acc[1][3]);
        acc[2][0] = fmaf(a.z, b.x, acc[2][0]); acc[2][1] = fmaf(a.z, b.y, acc[2][1]);
        acc[2][2] = fmaf(a.z, b.z, acc[2][2]); acc[2][3] = fmaf(a.z, b.w, acc[2][3]);
        acc[3][0] = fmaf(a.w, b.x, acc[3][0]); acc[3][1] = fmaf(a.w, b.y, acc[3][1]);
        acc[3][2] = fmaf(a.w, b.z, acc[3][2]); acc[3][3] = fmaf(a.w, b.w, acc[3][3]);
    }

#pragma unroll
    for (int i = 0; i < 4; i++) {
        int m = m0 + ty * 4 + i;
        if (m >= N_ATOMS) continue;
        int n = n0 + tx * 4;
        if (n < TROW) {
            float4 o = make_float4(acc[i][0], acc[i][1], acc[i][2], acc[i][3]);
            *(float4*)&g_T[(size_t)m * TROW + n] = o;
        }
    }
}

// ---------------------------------------------------------------------------
// Kernel 2: one warp per atom, 4 warps/CTA. Pair loop unrolled x2: two
// independent T-row load chains in flight (2x MLP vs before). Sense values
// live in registers (lane s owns sense[s]) and broadcast via shfl -- no smem,
// no syncwarp. Lanes 0..19 each own 4 output channels (float4).
// ---------------------------------------------------------------------------
__global__ __launch_bounds__(ATOMS_PER_BLK * 32) void pair_kernel(
    const float* __restrict__ dist,
    const float* __restrict__ coord,
    const float* __restrict__ selfb,
    const float* __restrict__ vecscales,
    const float* __restrict__ mu,
    const float* __restrict__ sigma,
    const int*   __restrict__ pf,
    const int*   __restrict__ ps,
    float*       __restrict__ out)
{
    const int lane = threadIdx.x & 31;
    const int a    = blockIdx.x * ATOMS_PER_BLK + (threadIdx.x >> 5);
    if (a >= N_ATOMS) return;

    // pair range: lane 0 binary-searches sorted pf, broadcast
    int start = 0, end = 0;
    if (lane == 0) {
        int lo = 0, hi = N_PAIRS;
        while (lo < hi) { int mid = (lo + hi) >> 1; if (pf[mid] < a) lo = mid + 1; else hi = mid; }
        start = lo;
        hi = N_PAIRS;
        while (lo < hi) { int mid = (lo + hi) >> 1; if (pf[mid] < a + 1) lo = mid + 1; else hi = mid; }
        end = lo;
    }
    start = __shfl_sync(0xffffffffu, start, 0);
    end   = __shfl_sync(0xffffffffu, end,   0);

    float mu_l = 0.f, cexp = 0.f;
    if (lane < ND) {
        mu_l = mu[lane];
        float sg = sigma[lane];
        cexp = -0.5f / (sg * sg);
    }

    float4 accS = make_float4(0.f, 0.f, 0.f, 0.f);
    float4 accX = accS, accY = accS, accZ = accS;

    const unsigned M20 = 0x000fffffu;
    int p = start;

    // ---- main loop: 2 pairs per iteration ----
    for (; p + 1 < end; p += 2) {
        const int   jA = ps[p],     jB = ps[p + 1];
        const float dA = dist[p],   dB = dist[p + 1];
        const float cAx = coord[3 * p + 0], cAy = coord[3 * p + 1], cAz = coord[3 * p + 2];
        const float cBx = coord[3 * p + 3], cBy = coord[3 * p + 4], cBz = coord[3 * p + 5];

        const float invA = __fdividef(1.f, dA);
        const float invB = __fdividef(1.f, dB);
        const float uxA = cAx * invA, uyA = cAy * invA, uzA = cAz * invA;
        const float uxB = cBx * invB, uyB = cBy * invB, uzB = cBz * invB;

        // per-lane sense (lane s owns sense[s]); all lanes compute (>=20 unused)
        float dfA = invA - mu_l;
        float dfB = invB - mu_l;
        float cutA = (dA < HARD_CUT_F) ? 0.5f * (__cosf((PI_F / HARD_CUT_F) * dA) + 1.f) : 0.f;
        float cutB = (dB < HARD_CUT_F) ? 0.5f * (__cosf((PI_F / HARD_CUT_F) * dB) + 1.f) : 0.f;
        float sA = __expf(cexp * dfA * dfA) * cutA;
        float sB = __expf(cexp * dfB * dfB) * cutB;

        if (lane < ND) {
            const float4* TA = (const float4*)(g_T + (size_t)jA * TROW);
            const float4* TB = (const float4*)(g_T + (size_t)jB * TROW);
            float4 vA = make_float4(0.f, 0.f, 0.f, 0.f);
            float4 vB = vA;
#pragma unroll
            for (int s = 0; s < ND; s++) {
                float4 ta = TA[s * 20 + lane];
                float4 tb = TB[s * 20 + lane];
                float svA = __shfl_sync(M20, sA, s);
                float svB = __shfl_sync(M20, sB, s);
                vA.x = fmaf(svA, ta.x, vA.x); vA.y = fmaf(svA, ta.y, vA.y);
                vA.z = fmaf(svA, ta.z, vA.z); vA.w = fmaf(svA, ta.w, vA.w);
                vB.x = fmaf(svB, tb.x, vB.x); vB.y = fmaf(svB, tb.y, vB.y);
                vB.z = fmaf(svB, tb.z, vB.z); vB.w = fmaf(svB, tb.w, vB.w);
            }
            accS.x += vA.x + vB.x; accS.y += vA.y + vB.y;
            accS.z += vA.z + vB.z; accS.w += vA.w + vB.w;
            accX.x = fmaf(uxA, vA.x, fmaf(uxB, vB.x, accX.x));
            accX.y = fmaf(uxA, vA.y, fmaf(uxB, vB.y, accX.y));
            accX.z = fmaf(uxA, vA.z, fmaf(uxB, vB.z, accX.z));
            accX.w = fmaf(uxA, vA.w, fmaf(uxB, vB.w, accX.w));
            accY.x = fmaf(uyA, vA.x, fmaf(uyB, vB.x, accY.x));
            accY.y = fmaf(uyA, vA.y, fmaf(uyB, vB.y, accY.y));
            accY.z = fmaf(uyA, vA.z, fmaf(uyB, vB.z, accY.z));
            accY.w = fmaf(uyA, vA.w, fmaf(uyB, vB.w, accY.w));
            accZ.x = fmaf(uzA, vA.x, fmaf(uzB, vB.x, accZ.x));
            accZ.y = fmaf(uzA, vA.y, fmaf(uzB, vB.y, accZ.y));
            accZ.z = fmaf(uzA, vA.z, fmaf(uzB, vB.z, accZ.z));
            accZ.w = fmaf(uzA, vA.w, fmaf(uzB, vB.w, accZ.w));
        }
    }

    // ---- tail: single remaining pair ----
    if (p < end) {
        const int   j = ps[p];
        const float d = dist[p];
        const float cx = coord[3 * p + 0], cy = coord[3 * p + 1], cz = coord[3 * p + 2];
        const float inv = __fdividef(1.f, d);
        const float ux = cx * inv, uy = cy * inv, uz = cz * inv;

        float df  = inv - mu_l;
        float cut = (d < HARD_CUT_F) ? 0.5f * (__cosf((PI_F / HARD_CUT_F) * d) + 1.f) : 0.f;
        float sv0 = __expf(cexp * df * df) * cut;

        if (lane < ND) {
            const float4* T = (const float4*)(g_T + (size_t)j * TROW);
            float4 v = make_float4(0.f, 0.f, 0.f, 0.f);
#pragma unroll
            for (int s = 0; s < ND; s++) {
                float4 tv = T[s * 20 + lane];
                float  sv = __shfl_sync(M20, sv0, s);
                v.x = fmaf(sv, tv.x, v.x); v.y = fmaf(sv, tv.y, v.y);
                v.z = fmaf(sv, tv.z, v.z); v.w = fmaf(sv, tv.w, v.w);
            }
            accS.x += v.x; accS.y += v.y; accS.z += v.z; accS.w += v.w;
            accX.x = fmaf(ux, v.x, accX.x); accX.y = fmaf(ux, v.y, accX.y);
            accX.z = fmaf(ux, v.z, accX.z); accX.w = fmaf(ux, v.w, accX.w);
            accY.x = fmaf(uy, v.x, accY.x); accY.y = fmaf(uy, v.y, accY.y);
            accY.z = fmaf(uy, v.z, accY.z); accY.w = fmaf(uy, v.w, accY.w);
            accZ.x = fmaf(uz, v.x, accZ.x); accZ.y = fmaf(uz, v.y, accZ.y);
            accZ.z = fmaf(uz, v.z, accZ.z); accZ.w = fmaf(uz, v.w, accZ.w);
        }
    }

    if (lane < ND) {
        // self-interaction slot precomputed in T (cols 1600..1679)
        const float4 sf = *(const float4*)(g_T + (size_t)a * TROW + 1600 + 4 * lane);
        const float4 vs = ((const float4*)vecscales)[lane];
        const float4 bb = ((const float4*)selfb)[lane];
        float4 o4;
        o4.x = accS.x + vs.x * sqrtf(accX.x * accX.x + accY.x * accY.x + accZ.x * accZ.x + 1e-30f) + sf.x + bb.x;
        o4.y = accS.y + vs.y * sqrtf(accX.y * accX.y + accY.y * accY.y + accZ.y * accZ.y + 1e-30f) + sf.y + bb.y;
        o4.z = accS.z + vs.z * sqrtf(accX.z * accX.z + accY.z * accY.z + accZ.z * accZ.z + 1e-30f) + sf.z + bb.z;
        o4.w = accS.w + vs.w * sqrtf(accX.w * accX.w + accY.w * accY.w + accZ.w * accZ.w + 1e-30f) + sf.w + bb.w;
        ((float4*)out)[a * 20 + lane] = o4;
    }
}

// ---------------------------------------------------------------------------
extern "C" void kernel_launch(void* const* d_in, const int* in_sizes, int n_in,
                              void* d_out, int out_size)
{
    const float* feat   = (const float*)d_in[0];   // [5000, 80]
    const float* dist   = (const float*)d_in[1];   // [200000]
    const float* coord  = (const float*)d_in[2];   // [200000, 3]
    const float* wint   = (const float*)d_in[3];   // [20, 80, 80]
    const float* wself  = (const float*)d_in[4];   // [80, 80]
    const float* sbias  = (const float*)d_in[5];   // [80]
    const float* vscale = (const float*)d_in[6];   // [80]
    const float* mu     = (const float*)d_in[7];   // [20]
    const float* sigma  = (const float*)d_in[8];   // [20]
    const int*   pf     = (const int*)d_in[9];     // [200000] sorted
    const int*   ps     = (const int*)d_in[10];    // [200000]
    float* out = (float*)d_out;                    // [5000, 80]

    dim3 g1((N_ATOMS + 63) / 64, (TROW + 63) / 64);   // 79 x 27
    tmat_kernel<<<g1, 256>>>(feat, wint, wself);
    pair_kernel<<<(N_ATOMS + ATOMS_PER_BLK - 1) / ATOMS_PER_BLK, ATOMS_PER_BLK * 32>>>(
        dist, coord, sbias, vscale, mu, sigma, pf, ps, out);
}